// round 1
// baseline (speedup 1.0000x reference)
#include <cuda_runtime.h>

// ============================================================================
// QuantumLayer: 4 qubits, 2 layers, BATCH=524288.
// State = 16 complex amps per sample, held entirely in registers.
// Prep kernel computes all weight-dependent trig (80 floats) once;
// copied to __constant__ for uniform-path broadcast loads in the main kernel.
//
// Layout of prep[80], per layer (stride 40):
//   [0..3]   cy[q]      (cos of RY half-angle)
//   [4..7]   sy[q]      (sin of RY half-angle)
//   [8..23]  ph_re[idx] (combined RZ diagonal phase, real)
//   [24..39] ph_im[idx] (combined RZ diagonal phase, imag)
// Phase for basis idx: exp(i * sum_q (bit_q ? +hz_q : -hz_q)), hz = 0.5*w_z.
// Bit convention: idx = b0*8 + b1*4 + b2*2 + b3 (wire q -> mask 1<<(3-q)).
// ============================================================================

__device__ float g_prep[80];
__constant__ float c_prep[80];

__global__ void prep_kernel(const float* __restrict__ w) {
    int t = threadIdx.x;  // launched with 32 threads
    if (t < 8) {
        int layer = t >> 2, q = t & 3;
        float hy = 0.5f * w[(layer * 4 + q) * 2 + 0];
        float s, c;
        sincosf(hy, &s, &c);
        g_prep[layer * 40 + q]     = c;
        g_prep[layer * 40 + 4 + q] = s;
    }
    {
        int layer = t >> 4, idx = t & 15;
        float ang = 0.0f;
        #pragma unroll
        for (int q = 0; q < 4; q++) {
            float hz = 0.5f * w[(layer * 4 + q) * 2 + 1];
            ang += ((idx >> (3 - q)) & 1) ? hz : -hz;
        }
        float s, c;
        sincosf(ang, &s, &c);
        g_prep[layer * 40 + 8 + idx]  = c;
        g_prep[layer * 40 + 24 + idx] = s;
    }
}

// ---- compile-time gate helpers (arrays fully register-promoted) ----

template <int M>
__device__ __forceinline__ void ry_real(float* ar, float cy, float sy) {
    #pragma unroll
    for (int i = 0; i < 16; i++) {
        if (!(i & M)) {
            int j = i | M;
            float a0 = ar[i], a1 = ar[j];
            ar[i] = cy * a0 - sy * a1;
            ar[j] = sy * a0 + cy * a1;
        }
    }
}

template <int M>
__device__ __forceinline__ void ry_cplx(float* ar, float* ai, float cy, float sy) {
    #pragma unroll
    for (int i = 0; i < 16; i++) {
        if (!(i & M)) {
            int j = i | M;
            float a0r = ar[i], a1r = ar[j];
            float a0i = ai[i], a1i = ai[j];
            ar[i] = cy * a0r - sy * a1r;
            ai[i] = cy * a0i - sy * a1i;
            ar[j] = sy * a0r + cy * a1r;
            ai[j] = sy * a0i + cy * a1i;
        }
    }
}

template <int CM, int TM>
__device__ __forceinline__ void cnot(float* ar, float* ai) {
    #pragma unroll
    for (int i = 0; i < 16; i++) {
        if ((i & CM) && !(i & TM)) {
            int j = i | TM;
            float t;
            t = ar[i]; ar[i] = ar[j]; ar[j] = t;
            t = ai[i]; ai[i] = ai[j]; ai[j] = t;
        }
    }
}

__global__ __launch_bounds__(256)
void circuit_kernel(const float* __restrict__ x, float* __restrict__ out, int B) {
    int b = blockIdx.x * blockDim.x + threadIdx.x;
    if (b >= B) return;

    float4 xv = reinterpret_cast<const float4*>(x)[b];
    float xa[4] = {xv.x, xv.y, xv.z, xv.w};

    // Encoding angles: h = tanh(x) * pi/2; fast tanh via __expf + fast divide.
    float ce[4], se[4];
    #pragma unroll
    for (int q = 0; q < 4; q++) {
        float e  = __expf(2.0f * xa[q]);
        float th = 1.0f - __fdividef(2.0f, e + 1.0f);     // tanh(x)
        __sincosf(th * 1.5707963267948966f, &se[q], &ce[q]);
    }

    // Product state after per-sample RY encoding (purely real).
    float m01[4], m23[4];
    m01[0] = ce[0] * ce[1]; m01[1] = ce[0] * se[1];
    m01[2] = se[0] * ce[1]; m01[3] = se[0] * se[1];
    m23[0] = ce[2] * ce[3]; m23[1] = ce[2] * se[3];
    m23[2] = se[2] * ce[3]; m23[3] = se[2] * se[3];

    float ar[16], ai[16];
    #pragma unroll
    for (int i = 0; i < 16; i++) ar[i] = m01[i >> 2] * m23[i & 3];

    // ---------------- layer 0 (state real through the RYs) ----------------
    ry_real<8>(ar, c_prep[0], c_prep[4]);
    ry_real<4>(ar, c_prep[1], c_prep[5]);
    ry_real<2>(ar, c_prep[2], c_prep[6]);
    ry_real<1>(ar, c_prep[3], c_prep[7]);

    // Combined RZ diagonal (real state * complex phase).
    #pragma unroll
    for (int i = 0; i < 16; i++) {
        float pr = c_prep[8 + i], pi = c_prep[24 + i];
        float r = ar[i];
        ar[i] = r * pr;
        ai[i] = r * pi;
    }

    cnot<8, 4>(ar, ai);   // CNOT(0,1)
    cnot<4, 2>(ar, ai);   // CNOT(1,2)
    cnot<2, 1>(ar, ai);   // CNOT(2,3)
    cnot<1, 8>(ar, ai);   // CNOT(3,0)

    // ---------------- layer 1 (complex) ----------------
    ry_cplx<8>(ar, ai, c_prep[40], c_prep[44]);
    ry_cplx<4>(ar, ai, c_prep[41], c_prep[45]);
    ry_cplx<2>(ar, ai, c_prep[42], c_prep[46]);
    ry_cplx<1>(ar, ai, c_prep[43], c_prep[47]);

    #pragma unroll
    for (int i = 0; i < 16; i++) {
        float pr = c_prep[48 + i], pi = c_prep[64 + i];
        float r = ar[i], im = ai[i];
        ar[i] = r * pr - im * pi;
        ai[i] = r * pi + im * pr;
    }

    cnot<8, 4>(ar, ai);
    cnot<4, 2>(ar, ai);
    cnot<2, 1>(ar, ai);
    cnot<1, 8>(ar, ai);

    // ---------------- measurement: <Z_q> via probability tree ----------------
    float p[16];
    #pragma unroll
    for (int i = 0; i < 16; i++) p[i] = ar[i] * ar[i] + ai[i] * ai[i];

    float s2[8], s4[4], s8[2];
    float z3 = 0.0f, z2 = 0.0f, z1 = 0.0f;
    #pragma unroll
    for (int j = 0; j < 8; j++) { s2[j] = p[2*j] + p[2*j+1]; z3 += p[2*j] - p[2*j+1]; }
    #pragma unroll
    for (int j = 0; j < 4; j++) { s4[j] = s2[2*j] + s2[2*j+1]; z2 += s2[2*j] - s2[2*j+1]; }
    #pragma unroll
    for (int j = 0; j < 2; j++) { s8[j] = s4[2*j] + s4[2*j+1]; z1 += s4[2*j] - s4[2*j+1]; }
    float z0 = s8[0] - s8[1];

    float4 o;
    o.x = z0; o.y = z1; o.z = z2; o.w = z3;
    reinterpret_cast<float4*>(out)[b] = o;
}

extern "C" void kernel_launch(void* const* d_in, const int* in_sizes, int n_in,
                              void* d_out, int out_size) {
    const float* x = (const float*)d_in[0];     // [B, 4]
    const float* w = (const float*)d_in[1];     // [2, 4, 2]
    float* out = (float*)d_out;                 // [B, 4]
    int B = in_sizes[0] / 4;

    prep_kernel<<<1, 32>>>(w);

    void* sym = nullptr;
    cudaGetSymbolAddress(&sym, g_prep);
    cudaMemcpyToSymbolAsync(c_prep, sym, 80 * sizeof(float), 0,
                            cudaMemcpyDeviceToDevice, 0);

    int threads = 256;
    int blocks = (B + threads - 1) / threads;
    circuit_kernel<<<blocks, threads>>>(x, out, B);
}

// round 2
// speedup vs baseline: 1.1358x; 1.1358x over previous
#include <cuda_runtime.h>

// ============================================================================
// QuantumLayer: 4 qubits, 2 layers, BATCH=524288. Single kernel.
//
// Reductions vs naive simulation:
//  - Encoding RY⊗4 on |0000> is a rank-1 real product state (24 muls).
//  - Per-layer RZs commute past other-wire RYs -> one 16-entry diagonal.
//  - Layer-1 diagonal is followed only by CNOTs (permutation) then |amp|^2,
//    so it cannot affect the output -> dropped entirely.
//  - CNOTs are compile-time register renames.
//  - Weight trig (24 sincos) computed once per block into smem by warp 0.
//  - Packed f32x2 math (SASS FFMA2): layer-1 complex RYs are lane-parallel
//    over {re,im}; layer-0 real RYs lane-parallel over amp pairs (qubit 3).
// ============================================================================

using u64 = unsigned long long;

__device__ __forceinline__ u64 mul2(u64 a, u64 b) {
    u64 d; asm("mul.rn.f32x2 %0, %1, %2;" : "=l"(d) : "l"(a), "l"(b)); return d;
}
__device__ __forceinline__ u64 fma2(u64 a, u64 b, u64 c) {
    u64 d; asm("fma.rn.f32x2 %0, %1, %2, %3;" : "=l"(d) : "l"(a), "l"(b), "l"(c)); return d;
}
__device__ __forceinline__ u64 pk(float lo, float hi) {
    u64 d; asm("mov.b64 %0, {%1, %2};" : "=l"(d) : "f"(lo), "f"(hi)); return d;
}
__device__ __forceinline__ float2 upk(u64 a) {
    float2 r; asm("mov.b64 {%0, %1}, %2;" : "=f"(r.x), "=f"(r.y) : "l"(a)); return r;
}

// Packed butterfly: (A0, A1) <- (c*A0 - s*A1, s*A0 + c*A1), lane-parallel.
__device__ __forceinline__ void bf2(u64& A0, u64& A1, u64 cc, u64 ss, u64 nss) {
    u64 t0 = A0, t1 = A1;
    A0 = fma2(t0, cc, mul2(t1, nss));
    A1 = fma2(t0, ss, mul2(t1, cc));
}

__global__ __launch_bounds__(256)
void circuit_kernel(const float* __restrict__ x, const float* __restrict__ w,
                    float* __restrict__ out, int B) {
    // ---- per-block prep: weight trig into smem ----
    // s_cy/s_sy[layer*4+q]; s_ph[idx] = {cos, sin} of layer-0 combined RZ angle.
    __shared__ float s_cy[8], s_sy[8];
    __shared__ u64   s_ph[16];

    int t = threadIdx.x;
    if (t < 8) {
        float hy = 0.5f * w[t * 2];
        float s, c; __sincosf(hy, &s, &c);
        s_cy[t] = c; s_sy[t] = s;
    } else if (t < 24) {
        int idx = t - 8;
        float ang = 0.0f;
        #pragma unroll
        for (int q = 0; q < 4; q++) {
            float hz = 0.5f * w[q * 2 + 1];   // layer 0, wire q, z-weight
            ang += ((idx >> (3 - q)) & 1) ? hz : -hz;
        }
        float s, c; __sincosf(ang, &s, &c);
        s_ph[idx] = pk(c, s);
    }
    __syncthreads();

    int b = blockIdx.x * blockDim.x + t;
    if (b >= B) return;

    float4 xv = reinterpret_cast<const float4*>(x)[b];
    float xa[4] = {xv.x, xv.y, xv.z, xv.w};

    // Encoding: half-angle h = tanh(x) * pi/2.
    float ce[4], se[4];
    #pragma unroll
    for (int q = 0; q < 4; q++) {
        float e  = __expf(2.0f * xa[q]);
        float th = 1.0f - __fdividef(2.0f, e + 1.0f);     // tanh
        __sincosf(th * 1.5707963267948966f, &se[q], &ce[q]);
    }

    // Real product state; packed pairs along qubit 3 (amp bit 0):
    // R[k] = {amp[2k], amp[2k+1]}, k = 0..7.
    float m01[4], m23[4];
    m01[0] = ce[0] * ce[1]; m01[1] = ce[0] * se[1];
    m01[2] = se[0] * ce[1]; m01[3] = se[0] * se[1];
    m23[0] = ce[2] * ce[3]; m23[1] = ce[2] * se[3];
    m23[2] = se[2] * ce[3]; m23[3] = se[2] * se[3];

    u64 R[8];
    #pragma unroll
    for (int k = 0; k < 8; k++) {
        float f = m01[k >> 1];
        R[k] = pk(f * m23[2 * (k & 1)], f * m23[2 * (k & 1) + 1]);
    }

    // ---- layer 0: RYs on real state (qubits 0..2 packed, pair-mask = M>>1) ----
    #pragma unroll
    for (int g = 0; g < 3; g++) {               // g = qubit index 0,1,2
        int m = 4 >> g;                          // pair mask
        float cy = s_cy[g], sy = s_sy[g];
        u64 cc = pk(cy, cy), ss = pk(sy, sy), nss = pk(-sy, -sy);
        #pragma unroll
        for (int k = 0; k < 8; k++)
            if (!(k & m)) bf2(R[k], R[k | m], cc, ss, nss);
    }

    // Qubit-3 RY (intra-pair, scalar) fused with layer-0 RZ diagonal.
    u64 A[16];
    {
        float cy = s_cy[3], sy = s_sy[3];
        #pragma unroll
        for (int k = 0; k < 8; k++) {
            float2 a = upk(R[k]);
            float n0 = cy * a.x - sy * a.y;
            float n1 = sy * a.x + cy * a.y;
            A[2 * k]     = mul2(pk(n0, n0), s_ph[2 * k]);
            A[2 * k + 1] = mul2(pk(n1, n1), s_ph[2 * k + 1]);
        }
    }

    // CNOT ring (register renames): (0,1) (1,2) (2,3) (3,0)
    #define CNOT(CM, TM)                                        \
        _Pragma("unroll")                                       \
        for (int i = 0; i < 16; i++)                            \
            if ((i & CM) && !(i & TM)) {                        \
                u64 tmp = A[i]; A[i] = A[i | TM]; A[i | TM] = tmp; \
            }
    CNOT(8, 4) CNOT(4, 2) CNOT(2, 1) CNOT(1, 8)

    // ---- layer 1: complex RYs, packed over {re,im} ----
    #pragma unroll
    for (int g = 0; g < 4; g++) {
        int M = 8 >> g;
        float cy = s_cy[4 + g], sy = s_sy[4 + g];
        u64 cc = pk(cy, cy), ss = pk(sy, sy), nss = pk(-sy, -sy);
        #pragma unroll
        for (int i = 0; i < 16; i++)
            if (!(i & M)) bf2(A[i], A[i | M], cc, ss, nss);
    }

    // Layer-1 RZ diagonal: |phase*amp|^2 == |amp|^2 after permutation -> skip.

    CNOT(8, 4) CNOT(4, 2) CNOT(2, 1) CNOT(1, 8)
    #undef CNOT

    // ---- measurement: probabilities + <Z_q> tree ----
    float p[16];
    #pragma unroll
    for (int i = 0; i < 16; i++) {
        float2 sq = upk(mul2(A[i], A[i]));
        p[i] = sq.x + sq.y;
    }

    float s2[8], s4[4], s8[2];
    float z3 = 0.0f, z2 = 0.0f, z1 = 0.0f;
    #pragma unroll
    for (int j = 0; j < 8; j++) { s2[j] = p[2*j] + p[2*j+1]; z3 += p[2*j] - p[2*j+1]; }
    #pragma unroll
    for (int j = 0; j < 4; j++) { s4[j] = s2[2*j] + s2[2*j+1]; z2 += s2[2*j] - s2[2*j+1]; }
    #pragma unroll
    for (int j = 0; j < 2; j++) { s8[j] = s4[2*j] + s4[2*j+1]; z1 += s4[2*j] - s4[2*j+1]; }
    float z0 = s8[0] - s8[1];

    float4 o; o.x = z0; o.y = z1; o.z = z2; o.w = z3;
    reinterpret_cast<float4*>(out)[b] = o;
}

extern "C" void kernel_launch(void* const* d_in, const int* in_sizes, int n_in,
                              void* d_out, int out_size) {
    const float* x = (const float*)d_in[0];     // [B, 4]
    const float* w = (const float*)d_in[1];     // [2, 4, 2]
    float* out = (float*)d_out;                 // [B, 4]
    int B = in_sizes[0] / 4;

    int threads = 256;
    int blocks = (B + threads - 1) / threads;
    circuit_kernel<<<blocks, threads>>>(x, w, out, B);
}